// round 16
// baseline (speedup 1.0000x reference)
#include <cuda_runtime.h>
#include <float.h>

// Chamfer-distance loss, fp32.
//   out = mean_i min_j max(||pred_i-gt_j||^2,0) + mean_j min_i max(...,0)
//
// d2 = p2 + (g2 - 2*dot); per-query p2 hoisted out of the min (monotone).
// Inner loop: 3-deep FMA chain per (query,target) pair, 2 targets at once
// via packed fp32x2 (PTX fma.rn.f32x2), NQ=4 queries/thread to amortize
// the 2 broadcast LDS.128 per target-pair.
//
// Persistent grid (296 = 148 SM x occ 2) over fine-grain (dir,ch,qb) items,
// ch-major so consecutive items reuse the smem target tile. Tile built
// in-kernel straight from gmem (no prep pass).

#define NTHR   256
#define NQ     4
#define QB     (NQ * NTHR)       // 1024 queries per item
#define TILE_T 256               // targets per tile (== NTHR, 1 target/thread build)
#define TILE_P (TILE_T / 2)
#define MAXT   24576
#define MAXC   96
#define GRID   296

__device__ float g_minpart[2][MAXC][MAXT];   // [dir][chunk][query] partial mins (excl. p2)
__device__ float g_partsum[512];             // block partial sums

// ---------- packed fp32x2 helpers ----------
__device__ __forceinline__ unsigned long long pack2(float a, float b) {
    unsigned long long r;
    asm("mov.b64 %0, {%1, %2};" : "=l"(r) : "f"(a), "f"(b));
    return r;
}
__device__ __forceinline__ void unpack2(unsigned long long v, float& a, float& b) {
    asm("mov.b64 {%0, %1}, %2;" : "=f"(a), "=f"(b) : "l"(v));
}
__device__ __forceinline__ unsigned long long fma2(unsigned long long a,
                                                   unsigned long long b,
                                                   unsigned long long c) {
    unsigned long long d;
    asm("fma.rn.f32x2 %0, %1, %2, %3;" : "=l"(d) : "l"(a), "l"(b), "l"(c));
    return d;
}

// ---------- main: persistent, tile-resident brute force ----------
__global__ __launch_bounds__(NTHR, 2)
void chamfer_main(const float* __restrict__ pred,
                  const float* __restrict__ gt,
                  int N, int M,
                  int nqb0, int nc0, int nqb1, int nc1) {
    __shared__ __align__(16) float s_tile[TILE_P][8];  // pair-interleaved: hx01 hy01 hz01 c01

    int items0 = nqb0 * nc0;                 // dir0: queries=pred, targets=gt
    int items  = items0 + nqb1 * nc1;        // dir1: queries=gt, targets=pred
    int lo = (int)((long long)blockIdx.x * items / gridDim.x);
    int hi = (int)((long long)(blockIdx.x + 1) * items / gridDim.x);
    if (lo >= hi) return;

    int cur_key = -1;
    for (int it = lo; it < hi; it++) {
        int dir, ch, qb;
        if (it < items0) { dir = 0; ch = it / nqb0; qb = it - ch * nqb0; }
        else { int u = it - items0; dir = 1; ch = u / nqb1; qb = u - ch * nqb1; }

        int key = (dir << 16) | ch;          // block-uniform
        if (key != cur_key) {
            __syncthreads();                 // prior readers of tile done
            // build tile: 1 target per thread, transformed to (-2x,-2y,-2z,|t|^2)
            int t = threadIdx.x;
            int j = ch * TILE_T + t;
            float x = 0.f, y = 0.f, z = 0.f, c = 1e30f;
            if (dir == 0) {
                if (j < M) {
                    float4 g = ((const float4*)gt)[j];   // gt stride 4
                    x = g.x; y = g.y; z = g.z;
                    c = x * x + y * y + z * z;
                }
            } else {
                if (j < N) {
                    x = pred[3 * j + 0];
                    y = pred[3 * j + 1];
                    z = pred[3 * j + 2];
                    c = x * x + y * y + z * z;
                }
            }
            int p = t >> 1, l = t & 1;
            s_tile[p][0 + l] = -2.f * x;
            s_tile[p][2 + l] = -2.f * y;
            s_tile[p][4 + l] = -2.f * z;
            s_tile[p][6 + l] = c;
            __syncthreads();
            cur_key = key;
        }

        // per-thread queries
        int nq_ = dir ? M : N;
        const float* qs = dir ? gt : pred;
        int qst = dir ? 4 : 3;

        unsigned long long px[NQ], py[NQ], pz[NQ];
        int qi[NQ];
        #pragma unroll
        for (int k = 0; k < NQ; k++) {
            int q = qb * QB + k * NTHR + threadIdx.x;
            qi[k] = q;
            float x = 0.f, y = 0.f, z = 0.f;
            if (q < nq_) {
                x = qs[q * qst + 0];
                y = qs[q * qst + 1];
                z = qs[q * qst + 2];
            }
            px[k] = pack2(x, x);
            py[k] = pack2(y, y);
            pz[k] = pack2(z, z);
        }

        float ma[NQ], mb[NQ];
        #pragma unroll
        for (int k = 0; k < NQ; k++) { ma[k] = FLT_MAX; mb[k] = FLT_MAX; }

        const ulonglong2* tp = (const ulonglong2*)&s_tile[0][0];
        #pragma unroll 4
        for (int p = 0; p < TILE_P; p++) {
            ulonglong2 A = tp[2 * p + 0];    // {hx01, hy01}
            ulonglong2 B = tp[2 * p + 1];    // {hz01, c01}
            #pragma unroll
            for (int k = 0; k < NQ; k++) {
                unsigned long long a = fma2(A.x, px[k], B.y);
                a = fma2(A.y, py[k], a);
                a = fma2(B.x, pz[k], a);
                float fl, fh; unpack2(a, fl, fh);
                ma[k] = fminf(ma[k], fl);
                mb[k] = fminf(mb[k], fh);
            }
        }

        #pragma unroll
        for (int k = 0; k < NQ; k++)
            if (qi[k] < nq_)
                g_minpart[dir][ch][qi[k]] = fminf(ma[k], mb[k]);
    }
}

// ---------- reduce1: min over chunks, add p2, relu, weight, block-sum ----------
__global__ void reduce1_kernel(const float* __restrict__ pred,
                               const float* __restrict__ gt,
                               int N, int M, int nc0, int nc1) {
    int i = blockIdx.x * blockDim.x + threadIdx.x;
    float v = 0.f;
    int total = N + M;
    if (i < total) {
        int dir = (i < N) ? 0 : 1;
        int q = dir ? (i - N) : i;
        int nc = dir ? nc1 : nc0;
        const float* base = &g_minpart[dir][0][q];
        float m0 = FLT_MAX, m1 = FLT_MAX, m2 = FLT_MAX, m3 = FLT_MAX;
        int c = 0;
        for (; c + 4 <= nc; c += 4) {
            m0 = fminf(m0, base[(c + 0) * MAXT]);
            m1 = fminf(m1, base[(c + 1) * MAXT]);
            m2 = fminf(m2, base[(c + 2) * MAXT]);
            m3 = fminf(m3, base[(c + 3) * MAXT]);
        }
        for (; c < nc; c++) m0 = fminf(m0, base[c * MAXT]);
        float m = fminf(fminf(m0, m1), fminf(m2, m3));
        const float* qs = dir ? gt : pred;
        int st = dir ? 4 : 3;
        float x = qs[q * st + 0], y = qs[q * st + 1], z = qs[q * st + 2];
        float p2 = x * x + y * y + z * z;
        float w = dir ? (1.f / (float)M) : (1.f / (float)N);
        v = fmaxf(m + p2, 0.f) * w;
    }
    __shared__ float ssum[256];
    ssum[threadIdx.x] = v;
    __syncthreads();
    for (int s = 128; s > 0; s >>= 1) {
        if (threadIdx.x < s) ssum[threadIdx.x] += ssum[threadIdx.x + s];
        __syncthreads();
    }
    if (threadIdx.x == 0) g_partsum[blockIdx.x] = ssum[0];
}

// ---------- reduce2: sum block partials ----------
__global__ void reduce2_kernel(float* __restrict__ out, int nparts) {
    float s = 0.f;
    for (int i = threadIdx.x; i < nparts; i += 256)
        s += g_partsum[i];
    __shared__ float ssum[256];
    ssum[threadIdx.x] = s;
    __syncthreads();
    for (int st = 128; st > 0; st >>= 1) {
        if (threadIdx.x < st) ssum[threadIdx.x] += ssum[threadIdx.x + st];
        __syncthreads();
    }
    if (threadIdx.x == 0) out[0] = ssum[0];
}

extern "C" void kernel_launch(void* const* d_in, const int* in_sizes, int n_in,
                              void* d_out, int out_size) {
    const float* pred = (const float*)d_in[0];  // [N,3]
    const float* gt   = (const float*)d_in[1];  // [M,4]
    int N = in_sizes[0] / 3;
    int M = in_sizes[1] / 4;

    int nc0  = (M + TILE_T - 1) / TILE_T;   // dir0 target chunks (gt)
    int nc1  = (N + TILE_T - 1) / TILE_T;   // dir1 target chunks (pred)
    int nqb0 = (N + QB - 1) / QB;           // dir0 query blocks (pred)
    int nqb1 = (M + QB - 1) / QB;           // dir1 query blocks (gt)

    chamfer_main<<<GRID, NTHR>>>(pred, gt, N, M, nqb0, nc0, nqb1, nc1);

    int total = N + M;
    int rblocks = (total + 255) / 256;
    reduce1_kernel<<<rblocks, 256>>>(pred, gt, N, M, nc0, nc1);
    reduce2_kernel<<<1, 256>>>((float*)d_out, rblocks);
}